// round 5
// baseline (speedup 1.0000x reference)
#include <cuda_runtime.h>
#include <math.h>

#define T_LEN   2000000
#define NTAGS   5
#define START_T 3
#define STOP_T  4

#define CHUNK   56
#define GRID1   140
#define BLOCK1  256
#define PAD     (GRID1 * BLOCK1)                      // 35840 lanes (padded)
#define LANES_ACT ((T_LEN - 1 + CHUNK - 1) / CHUNK)   // 35715
#define L_LAST    (LANES_ACT - 1)

#define TB_CH   64                                    // chunks per transpose block
#define TB_ROWS (TB_CH * CHUNK)                       // 3584 rows
#define NT_BLK  ((LANES_ACT + TB_CH - 1) / TB_CH)     // 559

// Phase-major staging: F_c[s*PAD + g] = feats[(1 + g*CHUNK + s)*5 + c]
__device__ float g_F0[CHUNK * PAD];
__device__ float g_F1[CHUNK * PAD];
__device__ float g_F2[CHUNK * PAD];
__device__ int   g_Tg[CHUNK * PAD];

__device__ float  g_Pinc[PAD][9];     // block-local inclusive matrix prefix (fp32)
__device__ int    g_pbinc[PAD];       // its power-of-2 base
__device__ float  g_gold[PAD];
__device__ float  g_Mblk[GRID1][9];   // per-block total
__device__ int    g_Bblk[GRID1];
__device__ double g_Eb[GRID1][9];     // block-exclusive prefix (double)
__device__ int    g_EbB[GRID1];
__device__ double g_u0[3];            // exp(v0 - c0)
__device__ double g_c0;
__device__ double g_part[PAD];
__device__ float  g_stop3[3];

__device__ __forceinline__ void renorm9(float* P, int& base) {
    float m = fmaxf(fmaxf(fmaxf(P[0], P[1]), fmaxf(P[2], P[3])),
                    fmaxf(fmaxf(P[4], P[5]), fmaxf(P[6], fmaxf(P[7], P[8]))));
    int e = (int)(__float_as_uint(m) >> 23) - 127;
    float sc = __uint_as_float((unsigned)(127 - e) << 23);
#pragma unroll
    for (int i = 0; i < 9; ++i) P[i] *= sc;
    base += e;
}

__device__ __forceinline__ void drenorm9(double* C, int& base) {
    double m = C[0];
#pragma unroll
    for (int i = 1; i < 9; ++i) m = fmax(m, C[i]);
    int e; frexp(m, &e);
    double sc = ldexp(1.0, -e);
#pragma unroll
    for (int i = 0; i < 9; ++i) C[i] *= sc;
    base += e;
}

// =============== K0: phase-major transpose (coalesced both sides via smem) ==========
__global__ void __launch_bounds__(256) k_transpose(
        const float* __restrict__ feats, const int* __restrict__ tags) {
    __shared__ float sF[3][TB_CH * 57];               // 57 stride: conflict-free reads
    int tid = threadIdx.x;
    long tbase = 1L + (long)blockIdx.x * TB_ROWS;
    int  Gbase = blockIdx.x * TB_CH;

    // coalesced read of feats rows (keep cols 0..2)
    for (int idx = tid; idx < TB_ROWS * 5; idx += 256) {
        int tl = idx / 5, c = idx - 5 * tl;
        long t = tbase + tl;
        if (c < 3 && t < T_LEN)
            sF[c][(tl / CHUNK) * 57 + (tl % CHUNK)] = feats[t * 5 + c];
    }
    __syncthreads();

    // coalesced phase-major writes
    for (int o = tid; o < CHUNK * TB_CH; o += 256) {
        int s = o / TB_CH, lg = o - TB_CH * s;
        int si = lg * 57 + s;
        long oo = (long)s * PAD + (Gbase + lg);
        g_F0[oo] = sF[0][si];
        g_F1[oo] = sF[1][si];
        g_F2[oo] = sF[2][si];
    }
    __syncthreads();

    // tags: reuse smem bank 0 as int storage
    int* sT = (int*)&sF[0][0];
    for (int tl = tid; tl < TB_ROWS; tl += 256) {
        long t = tbase + tl;
        if (t < T_LEN) sT[(tl / CHUNK) * 57 + (tl % CHUNK)] = tags[t];
    }
    __syncthreads();
    for (int o = tid; o < CHUNK * TB_CH; o += 256) {
        int s = o / TB_CH, lg = o - TB_CH * s;
        g_Tg[(long)s * PAD + (Gbase + lg)] = sT[lg * 57 + s];
    }
}

// =============== K1: exact chunk matrices + gold + in-block inclusive scan ==========
__global__ void __launch_bounds__(BLOCK1) k_chunks(
        const int* __restrict__ tags, const float* __restrict__ trans) {
    __shared__ float sP[BLOCK1][9];
    __shared__ int   sB[BLOCK1];
    __shared__ float sTr[25];

    const float L2E = 1.4426950408889634f;
    int tid = threadIdx.x;
    if (tid < 25) sTr[tid] = trans[tid];

    float Tl[9];
#pragma unroll
    for (int i = 0; i < 3; ++i)
#pragma unroll
        for (int k = 0; k < 3; ++k)
            Tl[i * 3 + k] = exp2f(L2E * __ldg(&trans[i * NTAGS + k]));
    __syncthreads();

    int g     = blockIdx.x * BLOCK1 + tid;
    int start = 1 + g * CHUNK;
    int n     = T_LEN - start; if (n > CHUNK) n = CHUNK;

    float P[9] = {1.f, 0.f, 0.f, 0.f, 1.f, 0.f, 0.f, 0.f, 1.f};
    int   base = 0;
    float gold = 0.f;

#define K1STEP() do {                                                        \
        float f0 = __ldg(p0), f1 = __ldg(p1), f2 = __ldg(p2);                \
        int cur = __ldg(pt);                                                 \
        p0 += PAD; p1 += PAD; p2 += PAD; pt += PAD;                          \
        float e0 = exp2f(L2E * f0), e1 = exp2f(L2E * f1), e2 = exp2f(L2E * f2);\
        float a0 = e0 * Tl[0], a1 = e0 * Tl[1], a2 = e0 * Tl[2];             \
        float b0 = e1 * Tl[3], b1 = e1 * Tl[4], b2 = e1 * Tl[5];             \
        float d0 = e2 * Tl[6], d1 = e2 * Tl[7], d2 = e2 * Tl[8];             \
        float q0 = a0*P[0] + a1*P[3] + a2*P[6];                              \
        float q1 = a0*P[1] + a1*P[4] + a2*P[7];                              \
        float q2 = a0*P[2] + a1*P[5] + a2*P[8];                              \
        float q3 = b0*P[0] + b1*P[3] + b2*P[6];                              \
        float q4 = b0*P[1] + b1*P[4] + b2*P[7];                              \
        float q5 = b0*P[2] + b1*P[5] + b2*P[8];                              \
        float q6 = d0*P[0] + d1*P[3] + d2*P[6];                              \
        float q7 = d0*P[1] + d1*P[4] + d2*P[7];                              \
        float q8 = d0*P[2] + d1*P[5] + d2*P[8];                              \
        P[0]=q0;P[1]=q1;P[2]=q2;P[3]=q3;P[4]=q4;P[5]=q5;P[6]=q6;P[7]=q7;P[8]=q8;\
        float emit = (cur == 0) ? f0 : ((cur == 1) ? f1 : f2);               \
        gold += emit + sTr[cur * NTAGS + prev];                              \
        prev = cur;                                                          \
    } while (0)

    if (n > 0) {
        int prev = __ldg(&tags[start - 1]);
        const float* p0 = g_F0 + g;
        const float* p1 = g_F1 + g;
        const float* p2 = g_F2 + g;
        const int*   pt = g_Tg + g;
        if (n == CHUNK) {
#pragma unroll 1
            for (int grp = 0; grp < CHUNK / 4; ++grp) {
#pragma unroll
                for (int k = 0; k < 4; ++k) K1STEP();
                renorm9(P, base);
            }
        } else {
            for (int s = 0; s < n; ++s) {
                K1STEP();
                if ((s & 3) == 3) renorm9(P, base);
            }
            renorm9(P, base);
        }
    }
#undef K1STEP

    g_gold[g] = gold;

    // Hillis-Steele inclusive scan of lane matrices (later on left)
#pragma unroll
    for (int i = 0; i < 9; ++i) sP[tid][i] = P[i];
    sB[tid] = base;
    __syncthreads();
    for (int s = 1; s < BLOCK1; s <<= 1) {
        float A[9], Bm[9], C[9]; int nb = 0; bool act = (tid >= s);
        if (act) {
#pragma unroll
            for (int i = 0; i < 9; ++i) { Bm[i] = sP[tid][i]; A[i] = sP[tid - s][i]; }
            nb = sB[tid] + sB[tid - s];
#pragma unroll
            for (int i = 0; i < 3; ++i)
#pragma unroll
                for (int j = 0; j < 3; ++j)
                    C[i*3+j] = Bm[i*3+0]*A[0+j] + Bm[i*3+1]*A[3+j] + Bm[i*3+2]*A[6+j];
            renorm9(C, nb);
        }
        __syncthreads();
        if (act) {
#pragma unroll
            for (int i = 0; i < 9; ++i) sP[tid][i] = C[i];
            sB[tid] = nb;
        }
        __syncthreads();
    }

#pragma unroll
    for (int i = 0; i < 9; ++i) g_Pinc[g][i] = sP[tid][i];
    g_pbinc[g] = sB[tid];
    if (tid == BLOCK1 - 1) {
#pragma unroll
        for (int i = 0; i < 9; ++i) g_Mblk[blockIdx.x][i] = sP[tid][i];
        g_Bblk[blockIdx.x] = sB[tid];
    }
}

// =============== K2: exclusive prefix over block totals (double) + v0 ===============
__global__ void __launch_bounds__(BLOCK1) k_blockscan(
        const float* __restrict__ feats, const float* __restrict__ trans) {
    __shared__ double sM[BLOCK1][9];
    __shared__ int    sb[BLOCK1];
    int tid = threadIdx.x;
    if (tid < GRID1) {
#pragma unroll
        for (int i = 0; i < 9; ++i) sM[tid][i] = (double)g_Mblk[tid][i];
        sb[tid] = g_Bblk[tid];
    } else {
#pragma unroll
        for (int i = 0; i < 9; ++i) sM[tid][i] = (i % 4 == 0) ? 1.0 : 0.0;
        sb[tid] = 0;
    }
    __syncthreads();
    for (int s = 1; s < BLOCK1; s <<= 1) {
        double A[9], Bm[9], C[9]; int nb = 0; bool act = (tid >= s);
        if (act) {
#pragma unroll
            for (int i = 0; i < 9; ++i) { Bm[i] = sM[tid][i]; A[i] = sM[tid - s][i]; }
            nb = sb[tid] + sb[tid - s];
#pragma unroll
            for (int i = 0; i < 3; ++i)
#pragma unroll
                for (int j = 0; j < 3; ++j)
                    C[i*3+j] = Bm[i*3+0]*A[0+j] + Bm[i*3+1]*A[3+j] + Bm[i*3+2]*A[6+j];
            drenorm9(C, nb);
        }
        __syncthreads();
        if (act) {
#pragma unroll
            for (int i = 0; i < 9; ++i) sM[tid][i] = C[i];
            sb[tid] = nb;
        }
        __syncthreads();
    }
    if (tid < GRID1) {
        if (tid == 0) {
#pragma unroll
            for (int i = 0; i < 9; ++i) g_Eb[0][i] = (i % 4 == 0) ? 1.0 : 0.0;
            g_EbB[0] = 0;
        } else {
#pragma unroll
            for (int i = 0; i < 9; ++i) g_Eb[tid][i] = sM[tid - 1][i];
            g_EbB[tid] = sb[tid - 1];
        }
    }
    if (tid == 0) {
        // v0 = fv after step t=0 (literal 5-state, double); store u0 = exp(v0-c0)
        double v0[3];
        for (int i = 0; i < 3; ++i) {
            double a[5]; double m = -1e300;
            for (int j = 0; j < 5; ++j) {
                a[j] = (double)trans[i * NTAGS + j] + ((j == START_T) ? 0.0 : -10000.0);
                if (a[j] > m) m = a[j];
            }
            double ss = 0.0;
            for (int j = 0; j < 5; ++j) ss += exp(a[j] - m);
            v0[i] = m + log(ss) + (double)feats[i];
        }
        double c0 = fmax(fmax(v0[0], v0[1]), v0[2]);
        g_c0 = c0;
        for (int j = 0; j < 3; ++j) g_u0[j] = exp(v0[j] - c0);
    }
}

// =============== K3: boundary vectors + fp32 absolute-scale emulation ===============
__global__ void __launch_bounds__(BLOCK1) k_emulate(const float* __restrict__ trans) {
    __shared__ float sTr[25];
    int tid = threadIdx.x;
    if (tid < 25) sTr[tid] = trans[tid];
    __syncthreads();

    int g = blockIdx.x * BLOCK1 + tid;
    if (g >= LANES_ACT) { g_part[g] = 0.0; return; }

    int b = blockIdx.x;
    double Eb[9]; int bE = g_EbB[b];
#pragma unroll
    for (int i = 0; i < 9; ++i) Eb[i] = g_Eb[b][i];
    double u0[3] = {g_u0[0], g_u0[1], g_u0[2]};
    double c0 = g_c0;
    const double LN2 = 0.6931471805599453;

    // A_g from lane-exclusive prefix (local inclusive of g-1, or identity)
    double ex[9]; int bL;
    if (tid == 0) {
#pragma unroll
        for (int i = 0; i < 9; ++i) ex[i] = (i % 4 == 0) ? 1.0 : 0.0;
        bL = 0;
    } else {
#pragma unroll
        for (int i = 0; i < 9; ++i) ex[i] = (double)g_Pinc[g - 1][i];
        bL = g_pbinc[g - 1];
    }
    float A0, A1, A2;
    {
        double Cd[9]; int baseg = bL + bE;
#pragma unroll
        for (int i = 0; i < 3; ++i)
#pragma unroll
            for (int j = 0; j < 3; ++j)
                Cd[i*3+j] = ex[i*3+0]*Eb[0+j] + ex[i*3+1]*Eb[3+j] + ex[i*3+2]*Eb[6+j];
        A0 = (float)(log(Cd[0]*u0[0] + Cd[1]*u0[1] + Cd[2]*u0[2]) + baseg * LN2 + c0);
        A1 = (float)(log(Cd[3]*u0[0] + Cd[4]*u0[1] + Cd[5]*u0[2]) + baseg * LN2 + c0);
        A2 = (float)(log(Cd[6]*u0[0] + Cd[7]*u0[1] + Cd[8]*u0[2]) + baseg * LN2 + c0);
    }
    // A_{g+1} from own inclusive prefix
    double Bn0, Bn1, Bn2;
    {
        double in9[9]; int bI = g_pbinc[g] + bE;
#pragma unroll
        for (int i = 0; i < 9; ++i) in9[i] = (double)g_Pinc[g][i];
        double Cn[9];
#pragma unroll
        for (int i = 0; i < 3; ++i)
#pragma unroll
            for (int j = 0; j < 3; ++j)
                Cn[i*3+j] = in9[i*3+0]*Eb[0+j] + in9[i*3+1]*Eb[3+j] + in9[i*3+2]*Eb[6+j];
        Bn0 = log(Cn[0]*u0[0] + Cn[1]*u0[1] + Cn[2]*u0[2]) + bI * LN2 + c0;
        Bn1 = log(Cn[3]*u0[0] + Cn[4]*u0[1] + Cn[5]*u0[2]) + bI * LN2 + c0;
        Bn2 = log(Cn[6]*u0[0] + Cn[7]*u0[1] + Cn[8]*u0[2]) + bI * LN2 + c0;
    }

    float fv0 = A0, fv1 = A1, fv2 = A2;
    int n = T_LEN - (1 + g * CHUNK); if (n > CHUNK) n = CHUNK;

    float t00 = sTr[0],  t01 = sTr[1],  t02 = sTr[2];
    float t10 = sTr[5],  t11 = sTr[6],  t12 = sTr[7];
    float t20 = sTr[10], t21 = sTr[11], t22 = sTr[12];

    const float* p0 = g_F0 + g;
    const float* p1 = g_F1 + g;
    const float* p2 = g_F2 + g;

#define EMSTEP() do {                                                        \
        float f0 = __ldg(p0), f1 = __ldg(p1), f2 = __ldg(p2);                \
        p0 += PAD; p1 += PAD; p2 += PAD;                                     \
        float a00=__fadd_rn(fv0,t00), a01=__fadd_rn(fv1,t01), a02=__fadd_rn(fv2,t02);\
        float a10=__fadd_rn(fv0,t10), a11=__fadd_rn(fv1,t11), a12=__fadd_rn(fv2,t12);\
        float a20=__fadd_rn(fv0,t20), a21=__fadd_rn(fv1,t21), a22=__fadd_rn(fv2,t22);\
        float m0=fmaxf(fmaxf(a00,a01),a02);                                  \
        float m1=fmaxf(fmaxf(a10,a11),a12);                                  \
        float m2=fmaxf(fmaxf(a20,a21),a22);                                  \
        float s0=__expf(a00-m0)+__expf(a01-m0)+__expf(a02-m0);               \
        float s1=__expf(a10-m1)+__expf(a11-m1)+__expf(a12-m1);               \
        float s2=__expf(a20-m2)+__expf(a21-m2)+__expf(a22-m2);               \
        fv0=__fadd_rn(__fadd_rn(__logf(s0),m0),f0);                          \
        fv1=__fadd_rn(__fadd_rn(__logf(s1),m1),f1);                          \
        fv2=__fadd_rn(__fadd_rn(__logf(s2),m2),f2);                          \
    } while (0)

    if (n == CHUNK) {
#pragma unroll 1
        for (int grp = 0; grp < CHUNK / 4; ++grp) {
#pragma unroll
            for (int k = 0; k < 4; ++k) EMSTEP();
        }
    } else {
        for (int s = 0; s < n; ++s) EMSTEP();
    }
#undef EMSTEP

    if (g < L_LAST) {
        g_part[g] = (((double)fv0 - Bn0) + ((double)fv1 - Bn1) + ((double)fv2 - Bn2)) / 3.0;
    } else {
        g_stop3[0] = __fadd_rn(fv0, sTr[STOP_T * NTAGS + 0]);
        g_stop3[1] = __fadd_rn(fv1, sTr[STOP_T * NTAGS + 1]);
        g_stop3[2] = __fadd_rn(fv2, sTr[STOP_T * NTAGS + 2]);
        g_part[g] = 0.0;
    }
}

// =============== K4: deterministic reductions + epilogue ===============
__global__ void __launch_bounds__(512) crf_out(
        const float* __restrict__ feats, const int* __restrict__ tags,
        const float* __restrict__ trans, float* __restrict__ out) {
    __shared__ double red[512];
    int tid = threadIdx.x;

    double s = 0.0;
    for (int i = tid; i < PAD; i += 512) s += g_part[i];
    red[tid] = s; __syncthreads();
    for (int k = 256; k > 0; k >>= 1) {
        if (tid < k) red[tid] += red[tid + k];
        __syncthreads();
    }
    double mu = red[0]; __syncthreads();

    double sg = 0.0;
    for (int i = tid; i < PAD; i += 512) sg += (double)g_gold[i];
    red[tid] = sg; __syncthreads();
    for (int k = 256; k > 0; k >>= 1) {
        if (tid < k) red[tid] += red[tid + k];
        __syncthreads();
    }
    double goldsum = red[0];

    if (tid == 0) {
        double b0 = (double)g_stop3[0], b1 = (double)g_stop3[1], b2 = (double)g_stop3[2];
        double m = fmax(fmax(b0, b1), b2);
        double alpha = m + log(exp(b0 - m) + exp(b1 - m) + exp(b2 - m)) + mu;

        int tg0 = tags[0];
        int tgL = tags[T_LEN - 1];
        double gold = goldsum
                    + (double)trans[tg0 * NTAGS + START_T]
                    + (double)feats[tg0]
                    + (double)trans[STOP_T * NTAGS + tgL];
        out[0] = (float)(alpha - gold);
    }
}

extern "C" void kernel_launch(void* const* d_in, const int* in_sizes, int n_in,
                              void* d_out, int out_size) {
    const float* feats = nullptr;
    const int*   tags  = nullptr;
    const float* trans = nullptr;
    for (int i = 0; i < n_in; ++i) {
        if (in_sizes[i] == NTAGS * NTAGS)      trans = (const float*)d_in[i];
        else if (in_sizes[i] == T_LEN)         tags  = (const int*)d_in[i];
        else                                   feats = (const float*)d_in[i];
    }
    float* out = (float*)d_out;

    k_transpose<<<NT_BLK, 256>>>(feats, tags);
    k_chunks<<<GRID1, BLOCK1>>>(tags, trans);
    k_blockscan<<<1, BLOCK1>>>(feats, trans);
    k_emulate<<<GRID1, BLOCK1>>>(trans);
    crf_out<<<1, 512>>>(feats, tags, trans, out);
}

// round 6
// speedup vs baseline: 2.1290x; 2.1290x over previous
#include <cuda_runtime.h>
#include <math.h>

#define T_LEN   2000000
#define NTAGS   5
#define START_T 3
#define STOP_T  4

#define CHUNK   14
#define BLOCK1  256
#define LANES_ACT ((T_LEN - 1 + CHUNK - 1) / CHUNK)   // 142858
#define L_LAST    (LANES_ACT - 1)
#define NBLK      ((LANES_ACT + BLOCK1 - 1) / BLOCK1) // 559
#define PAD       (NBLK * BLOCK1)                     // 143104

#define TB_CH   128
#define TB_ROWS (TB_CH * CHUNK)                       // 1792
#define NT_BLK  ((LANES_ACT + TB_CH - 1) / TB_CH)     // 1117
#define SSTR    (CHUNK + 1)                           // 15

#define LN2_D   0.6931471805599453

// Phase-major staging: F_c[s*PAD + g] = feats[(1 + g*CHUNK + s)*5 + c]
__device__ float g_F0[CHUNK * PAD];
__device__ float g_F1[CHUNK * PAD];
__device__ float g_F2[CHUNK * PAD];
__device__ int   g_Tg[CHUNK * PAD];

__device__ float  g_Pinc[9 * PAD];    // block-local inclusive matrix prefix (SoA)
__device__ int    g_pbinc[PAD];
__device__ float  g_goldB[NBLK];      // per-block gold sums (ordered tree)
__device__ float  g_Mblk[NBLK][9];    // per-block matrix totals
__device__ int    g_Bblk[NBLK];
__device__ float  g_Ebf[NBLK][9];     // block-exclusive prefix (fp32 + base)
__device__ int    g_EbB[NBLK];
__device__ float  g_u0f[3];
__device__ double g_c0d;
__device__ double g_partB[NBLK];      // per-block telescoping sums
__device__ float  g_stop3[3];

__device__ __forceinline__ void renorm9(float* P, int& base) {
    float m = fmaxf(fmaxf(fmaxf(P[0], P[1]), fmaxf(P[2], P[3])),
                    fmaxf(fmaxf(P[4], P[5]), fmaxf(P[6], fmaxf(P[7], P[8]))));
    int e = (int)(__float_as_uint(m) >> 23) - 127;
    float sc = __uint_as_float((unsigned)(127 - e) << 23);
#pragma unroll
    for (int i = 0; i < 9; ++i) P[i] *= sc;
    base += e;
}

__device__ __forceinline__ void mm9(const float* Bm, const float* A, float* C) {
#pragma unroll
    for (int i = 0; i < 3; ++i)
#pragma unroll
        for (int j = 0; j < 3; ++j)
            C[i*3+j] = Bm[i*3+0]*A[0+j] + Bm[i*3+1]*A[3+j] + Bm[i*3+2]*A[6+j];
}

// Boundary vector: A_i = log( (Pm x Eb) . u0 ) + (bP+bE)*ln2 + c0   (all fp32 core)
__device__ __forceinline__ void boundaryA(const float* Pm, int bP,
                                          const float* Eb, int bE,
                                          const float* u0, double c0d,
                                          float* out3) {
    float Cd[9];
    mm9(Pm, Eb, Cd);
    double t = (double)(bP + bE) * LN2_D + c0d;
#pragma unroll
    for (int i = 0; i < 3; ++i) {
        float w = Cd[i*3+0]*u0[0] + Cd[i*3+1]*u0[1] + Cd[i*3+2]*u0[2];
        out3[i] = (float)((double)__logf(w) + t);
    }
}

// =============== K0: phase-major transpose ===============
__global__ void __launch_bounds__(256) k_transpose(
        const float* __restrict__ feats, const int* __restrict__ tags) {
    __shared__ float sF[3][TB_CH * SSTR];
    int tid = threadIdx.x;
    int tbase = 1 + blockIdx.x * TB_ROWS;
    int Gbase = blockIdx.x * TB_CH;

    for (int idx = tid; idx < TB_ROWS * 5; idx += 256) {
        int tl = idx / 5, c = idx - 5 * tl;
        int t = tbase + tl;
        if (c < 3 && t < T_LEN)
            sF[c][(tl / CHUNK) * SSTR + (tl % CHUNK)] = feats[t * 5 + c];
    }
    __syncthreads();

    for (int o = tid; o < CHUNK * TB_CH; o += 256) {
        int s = o / TB_CH, lg = o - TB_CH * s;
        int si = lg * SSTR + s;
        int oo = s * PAD + (Gbase + lg);
        g_F0[oo] = sF[0][si];
        g_F1[oo] = sF[1][si];
        g_F2[oo] = sF[2][si];
    }
    __syncthreads();

    int* sT = (int*)&sF[0][0];
    for (int tl = tid; tl < TB_ROWS; tl += 256) {
        int t = tbase + tl;
        if (t < T_LEN) sT[(tl / CHUNK) * SSTR + (tl % CHUNK)] = tags[t];
    }
    __syncthreads();
    for (int o = tid; o < CHUNK * TB_CH; o += 256) {
        int s = o / TB_CH, lg = o - TB_CH * s;
        g_Tg[s * PAD + (Gbase + lg)] = sT[lg * SSTR + s];
    }
}

// =============== K1: exact chunk matrices + gold + in-block scan ===============
__global__ void __launch_bounds__(BLOCK1) k_chunks(
        const int* __restrict__ tags, const float* __restrict__ trans) {
    __shared__ float sP[BLOCK1][9];
    __shared__ int   sB[BLOCK1];
    __shared__ float sG[BLOCK1];
    __shared__ float sTr[25];

    const float L2E = 1.4426950408889634f;
    int tid = threadIdx.x;
    if (tid < 25) sTr[tid] = trans[tid];

    float Tl[9];
#pragma unroll
    for (int i = 0; i < 3; ++i)
#pragma unroll
        for (int k = 0; k < 3; ++k)
            Tl[i * 3 + k] = exp2f(L2E * __ldg(&trans[i * NTAGS + k]));
    __syncthreads();

    int g     = blockIdx.x * BLOCK1 + tid;
    int start = 1 + g * CHUNK;
    int n     = (g < LANES_ACT) ? min(CHUNK, T_LEN - start) : 0;

    float P[9] = {1.f, 0.f, 0.f, 0.f, 1.f, 0.f, 0.f, 0.f, 1.f};
    int   base = 0;
    float gold = 0.f;

#define K1STEP() do {                                                        \
        float f0 = __ldg(p0), f1 = __ldg(p1), f2 = __ldg(p2);                \
        int cur = __ldg(pt);                                                 \
        p0 += PAD; p1 += PAD; p2 += PAD; pt += PAD;                          \
        float e0 = exp2f(L2E * f0), e1 = exp2f(L2E * f1), e2 = exp2f(L2E * f2);\
        float a0 = e0 * Tl[0], a1 = e0 * Tl[1], a2 = e0 * Tl[2];             \
        float b0 = e1 * Tl[3], b1 = e1 * Tl[4], b2 = e1 * Tl[5];             \
        float d0 = e2 * Tl[6], d1 = e2 * Tl[7], d2 = e2 * Tl[8];             \
        float q0 = a0*P[0] + a1*P[3] + a2*P[6];                              \
        float q1 = a0*P[1] + a1*P[4] + a2*P[7];                              \
        float q2 = a0*P[2] + a1*P[5] + a2*P[8];                              \
        float q3 = b0*P[0] + b1*P[3] + b2*P[6];                              \
        float q4 = b0*P[1] + b1*P[4] + b2*P[7];                              \
        float q5 = b0*P[2] + b1*P[5] + b2*P[8];                              \
        float q6 = d0*P[0] + d1*P[3] + d2*P[6];                              \
        float q7 = d0*P[1] + d1*P[4] + d2*P[7];                              \
        float q8 = d0*P[2] + d1*P[5] + d2*P[8];                              \
        P[0]=q0;P[1]=q1;P[2]=q2;P[3]=q3;P[4]=q4;P[5]=q5;P[6]=q6;P[7]=q7;P[8]=q8;\
        float emit = (cur == 0) ? f0 : ((cur == 1) ? f1 : f2);               \
        gold += emit + sTr[cur * NTAGS + prev];                              \
        prev = cur;                                                          \
    } while (0)

    if (n > 0) {
        int prev = __ldg(&tags[start - 1]);
        const float* p0 = g_F0 + g;
        const float* p1 = g_F1 + g;
        const float* p2 = g_F2 + g;
        const int*   pt = g_Tg + g;
        if (n == CHUNK) {
#pragma unroll
            for (int s = 0; s < 7; ++s) K1STEP();
            renorm9(P, base);
#pragma unroll
            for (int s = 0; s < 7; ++s) K1STEP();
            renorm9(P, base);
        } else {
            for (int s = 0; s < n; ++s) {
                K1STEP();
                if ((s & 7) == 6) renorm9(P, base);
            }
            renorm9(P, base);
        }
    }
#undef K1STEP

    // per-block gold (ordered tree)
    sG[tid] = gold;
    __syncthreads();
    for (int k = BLOCK1 / 2; k > 0; k >>= 1) {
        if (tid < k) sG[tid] += sG[tid + k];
        __syncthreads();
    }
    if (tid == 0) g_goldB[blockIdx.x] = sG[0];

    // Hillis-Steele inclusive scan of lane matrices (later on left)
#pragma unroll
    for (int i = 0; i < 9; ++i) sP[tid][i] = P[i];
    sB[tid] = base;
    __syncthreads();
    for (int s = 1; s < BLOCK1; s <<= 1) {
        float A[9], C[9]; int nb = 0; bool act = (tid >= s);
        if (act) {
            float Bm[9];
#pragma unroll
            for (int i = 0; i < 9; ++i) { Bm[i] = sP[tid][i]; A[i] = sP[tid - s][i]; }
            nb = sB[tid] + sB[tid - s];
            mm9(Bm, A, C);
            renorm9(C, nb);
        }
        __syncthreads();
        if (act) {
#pragma unroll
            for (int i = 0; i < 9; ++i) sP[tid][i] = C[i];
            sB[tid] = nb;
        }
        __syncthreads();
    }

#pragma unroll
    for (int i = 0; i < 9; ++i) g_Pinc[i * PAD + g] = sP[tid][i];
    g_pbinc[g] = sB[tid];
    if (tid == BLOCK1 - 1) {
#pragma unroll
        for (int i = 0; i < 9; ++i) g_Mblk[blockIdx.x][i] = sP[tid][i];
        g_Bblk[blockIdx.x] = sB[tid];
    }
}

// =============== K2: exclusive prefix over NBLK block totals (fp32+base) ===========
#define K2_ITEMS 3                       // 256*3 = 768 >= NBLK
__global__ void __launch_bounds__(BLOCK1) k_blockscan(
        const float* __restrict__ feats, const float* __restrict__ trans) {
    __shared__ float sM[BLOCK1][9];
    __shared__ int   sb[BLOCK1];
    int tid = threadIdx.x;

    float loc[K2_ITEMS][9]; int lb[K2_ITEMS];
    float tot[9] = {1.f,0.f,0.f, 0.f,1.f,0.f, 0.f,0.f,1.f};
    int   bt = 0;
#pragma unroll
    for (int k = 0; k < K2_ITEMS; ++k) {
        int i = tid * K2_ITEMS + k;
        if (i < NBLK) {
#pragma unroll
            for (int j = 0; j < 9; ++j) loc[k][j] = g_Mblk[i][j];
            lb[k] = g_Bblk[i];
            float C[9];
            mm9(loc[k], tot, C);
            bt += lb[k];
            renorm9(C, bt);
#pragma unroll
            for (int j = 0; j < 9; ++j) tot[j] = C[j];
        } else {
#pragma unroll
            for (int j = 0; j < 9; ++j) loc[k][j] = (j % 4 == 0) ? 1.f : 0.f;
            lb[k] = 0;
        }
    }
#pragma unroll
    for (int j = 0; j < 9; ++j) sM[tid][j] = tot[j];
    sb[tid] = bt;
    __syncthreads();

    for (int s = 1; s < BLOCK1; s <<= 1) {
        float A[9], C[9]; int nb = 0; bool act = (tid >= s);
        if (act) {
            float Bm[9];
#pragma unroll
            for (int j = 0; j < 9; ++j) { Bm[j] = sM[tid][j]; A[j] = sM[tid - s][j]; }
            nb = sb[tid] + sb[tid - s];
            mm9(Bm, A, C);
            renorm9(C, nb);
        }
        __syncthreads();
        if (act) {
#pragma unroll
            for (int j = 0; j < 9; ++j) sM[tid][j] = C[j];
            sb[tid] = nb;
        }
        __syncthreads();
    }

    float E[9]; int be;
    if (tid == 0) {
#pragma unroll
        for (int j = 0; j < 9; ++j) E[j] = (j % 4 == 0) ? 1.f : 0.f;
        be = 0;
    } else {
#pragma unroll
        for (int j = 0; j < 9; ++j) E[j] = sM[tid - 1][j];
        be = sb[tid - 1];
    }
#pragma unroll
    for (int k = 0; k < K2_ITEMS; ++k) {
        int i = tid * K2_ITEMS + k;
        if (i < NBLK) {
#pragma unroll
            for (int j = 0; j < 9; ++j) g_Ebf[i][j] = E[j];
            g_EbB[i] = be;
            float C[9];
            mm9(loc[k], E, C);
            be += lb[k];
            renorm9(C, be);
#pragma unroll
            for (int j = 0; j < 9; ++j) E[j] = C[j];
        }
    }

    if (tid == 0) {
        // v0 = fv after step t=0 (literal 5-state, double)
        double v0[3];
        for (int i = 0; i < 3; ++i) {
            double a[5]; double m = -1e300;
            for (int j = 0; j < 5; ++j) {
                a[j] = (double)trans[i * NTAGS + j] + ((j == START_T) ? 0.0 : -10000.0);
                if (a[j] > m) m = a[j];
            }
            double ss = 0.0;
            for (int j = 0; j < 5; ++j) ss += exp(a[j] - m);
            v0[i] = m + log(ss) + (double)feats[i];
        }
        double c0 = fmax(fmax(v0[0], v0[1]), v0[2]);
        g_c0d = c0;
        for (int j = 0; j < 3; ++j) g_u0f[j] = (float)exp(v0[j] - c0);
    }
}

// =============== K3: boundary vectors + fp32 absolute-scale emulation ===============
__global__ void __launch_bounds__(BLOCK1) k_emulate(const float* __restrict__ trans) {
    __shared__ float  sTr[25];
    __shared__ double sPart[BLOCK1];
    int tid = threadIdx.x;
    if (tid < 25) sTr[tid] = trans[tid];
    __syncthreads();

    int g = blockIdx.x * BLOCK1 + tid;
    double part = 0.0;

    if (g < LANES_ACT) {
        int b = blockIdx.x;
        float Eb[9]; int bE = g_EbB[b];
#pragma unroll
        for (int i = 0; i < 9; ++i) Eb[i] = g_Ebf[b][i];
        float u0[3] = {g_u0f[0], g_u0f[1], g_u0f[2]};
        double c0d = g_c0d;

        // start vector A_g (exclusive local prefix x block prefix)
        float ex[9]; int bL;
        if (tid == 0) {
#pragma unroll
            for (int i = 0; i < 9; ++i) ex[i] = (i % 4 == 0) ? 1.f : 0.f;
            bL = 0;
        } else {
#pragma unroll
            for (int i = 0; i < 9; ++i) ex[i] = g_Pinc[i * PAD + (g - 1)];
            bL = g_pbinc[g - 1];
        }
        float A[3];
        boundaryA(ex, bL, Eb, bE, u0, c0d, A);

        // target vector A_{g+1} (own inclusive prefix) — identical expression
        float in9[9];
#pragma unroll
        for (int i = 0; i < 9; ++i) in9[i] = g_Pinc[i * PAD + g];
        int bI = g_pbinc[g];
        float Bn[3];
        boundaryA(in9, bI, Eb, bE, u0, c0d, Bn);

        float fv0 = A[0], fv1 = A[1], fv2 = A[2];
        int n = min(CHUNK, T_LEN - (1 + g * CHUNK));

        float t00 = sTr[0],  t01 = sTr[1],  t02 = sTr[2];
        float t10 = sTr[5],  t11 = sTr[6],  t12 = sTr[7];
        float t20 = sTr[10], t21 = sTr[11], t22 = sTr[12];

        const float* p0 = g_F0 + g;
        const float* p1 = g_F1 + g;
        const float* p2 = g_F2 + g;

#define EMSTEP() do {                                                        \
        float f0 = __ldg(p0), f1 = __ldg(p1), f2 = __ldg(p2);                \
        p0 += PAD; p1 += PAD; p2 += PAD;                                     \
        float a00=__fadd_rn(fv0,t00), a01=__fadd_rn(fv1,t01), a02=__fadd_rn(fv2,t02);\
        float a10=__fadd_rn(fv0,t10), a11=__fadd_rn(fv1,t11), a12=__fadd_rn(fv2,t12);\
        float a20=__fadd_rn(fv0,t20), a21=__fadd_rn(fv1,t21), a22=__fadd_rn(fv2,t22);\
        float m0=fmaxf(fmaxf(a00,a01),a02);                                  \
        float m1=fmaxf(fmaxf(a10,a11),a12);                                  \
        float m2=fmaxf(fmaxf(a20,a21),a22);                                  \
        float s0=__expf(a00-m0)+__expf(a01-m0)+__expf(a02-m0);               \
        float s1=__expf(a10-m1)+__expf(a11-m1)+__expf(a12-m1);               \
        float s2=__expf(a20-m2)+__expf(a21-m2)+__expf(a22-m2);               \
        fv0=__fadd_rn(__fadd_rn(__logf(s0),m0),f0);                          \
        fv1=__fadd_rn(__fadd_rn(__logf(s1),m1),f1);                          \
        fv2=__fadd_rn(__fadd_rn(__logf(s2),m2),f2);                          \
    } while (0)

        if (n == CHUNK) {
#pragma unroll
            for (int s = 0; s < CHUNK; ++s) EMSTEP();
        } else {
            for (int s = 0; s < n; ++s) EMSTEP();
        }
#undef EMSTEP

        if (g < L_LAST) {
            // O and A within 2x -> subtraction exact (Sterbenz)
            part = (((double)fv0 - (double)Bn[0])
                  + ((double)fv1 - (double)Bn[1])
                  + ((double)fv2 - (double)Bn[2])) / 3.0;
        } else {
            g_stop3[0] = __fadd_rn(fv0, sTr[STOP_T * NTAGS + 0]);
            g_stop3[1] = __fadd_rn(fv1, sTr[STOP_T * NTAGS + 1]);
            g_stop3[2] = __fadd_rn(fv2, sTr[STOP_T * NTAGS + 2]);
            part = 0.0;
        }
    }

    sPart[tid] = part;
    __syncthreads();
    for (int k = BLOCK1 / 2; k > 0; k >>= 1) {
        if (tid < k) sPart[tid] += sPart[tid + k];
        __syncthreads();
    }
    if (tid == 0) g_partB[blockIdx.x] = sPart[0];
}

// =============== K4: final reductions + epilogue ===============
__global__ void __launch_bounds__(512) crf_out(
        const float* __restrict__ feats, const int* __restrict__ tags,
        const float* __restrict__ trans, float* __restrict__ out) {
    __shared__ double red[512];
    int tid = threadIdx.x;

    double s = 0.0;
    for (int i = tid; i < NBLK; i += 512) s += g_partB[i];
    red[tid] = s; __syncthreads();
    for (int k = 256; k > 0; k >>= 1) {
        if (tid < k) red[tid] += red[tid + k];
        __syncthreads();
    }
    double mu = red[0]; __syncthreads();

    double sg = 0.0;
    for (int i = tid; i < NBLK; i += 512) sg += (double)g_goldB[i];
    red[tid] = sg; __syncthreads();
    for (int k = 256; k > 0; k >>= 1) {
        if (tid < k) red[tid] += red[tid + k];
        __syncthreads();
    }
    double goldsum = red[0];

    if (tid == 0) {
        double b0 = (double)g_stop3[0], b1 = (double)g_stop3[1], b2 = (double)g_stop3[2];
        double m = fmax(fmax(b0, b1), b2);
        double alpha = m + log(exp(b0 - m) + exp(b1 - m) + exp(b2 - m)) + mu;

        int tg0 = tags[0];
        int tgL = tags[T_LEN - 1];
        double gold = goldsum
                    + (double)trans[tg0 * NTAGS + START_T]
                    + (double)feats[tg0]
                    + (double)trans[STOP_T * NTAGS + tgL];
        out[0] = (float)(alpha - gold);
    }
}

extern "C" void kernel_launch(void* const* d_in, const int* in_sizes, int n_in,
                              void* d_out, int out_size) {
    const float* feats = nullptr;
    const int*   tags  = nullptr;
    const float* trans = nullptr;
    for (int i = 0; i < n_in; ++i) {
        if (in_sizes[i] == NTAGS * NTAGS)      trans = (const float*)d_in[i];
        else if (in_sizes[i] == T_LEN)         tags  = (const int*)d_in[i];
        else                                   feats = (const float*)d_in[i];
    }
    float* out = (float*)d_out;

    k_transpose<<<NT_BLK, 256>>>(feats, tags);
    k_chunks<<<NBLK, BLOCK1>>>(tags, trans);
    k_blockscan<<<1, BLOCK1>>>(feats, trans);
    k_emulate<<<NBLK, BLOCK1>>>(trans);
    crf_out<<<1, 512>>>(feats, tags, trans, out);
}